// round 5
// baseline (speedup 1.0000x reference)
#include <cuda_runtime.h>

// ---------------------------------------------------------------------------
// WaveletEncoder: 2-level Haar wavedec2 -> bilinear(antialias) resize to 8x8
// -> stack 7 maps -> [B,64,7] @ W[7,256] + b.
//
// All-linear separable pipeline; axes commute; triangle antialias resize
// weight is linear within blocks of K/2 samples => per-block (sum, moment).
//
// Round-5:
//   k1 (fused, 512 thr, 2 cols/thread): stream 64 rows accumulating 8 H-axis
//     moment types per column; W-axis Haar levels: level1 pair = intra-thread,
//     level2 pair = lane-parity shfl; warp == W-block t (tid>>5); per H-moment
//     chunk an 8-value butterfly reduces the 8 W-moments across the warp into
//     smem [t][mtH][wm]; final combine (256 thr) applies analytic resize
//     coefficient tables -> V[imgb][8][32].
//   k3 (grid 64x4): V -> Y[32][32] -> 7 maps' 8x8 feats -> GEMM W[7,256]+b,
//     each block writes 16 of the 64 output positions.
// ---------------------------------------------------------------------------

#define FULLMASK 0xffffffffu

__device__ float g_V[64u * 16u * 8u * 32u];  // 1 MB [imgb][8 mtH][32 z]

static __device__ __forceinline__ void resize_ab(int o, int t, float K,
                                                 float invK, float fold,
                                                 float &a, float &b) {
    float tot = K * ((o == 0 || o == 7) ? 0.875f : 1.0f);
    float sf = (o + 0.5f) * K - 0.5f;
    float i0 = t * (K * 0.5f);
    float w0 = fmaxf(0.f, 1.f - fabsf(sf - i0) * invK);
    float w1 = fmaxf(0.f, 1.f - fabsf(sf - (i0 + 1.f)) * invK);
    float s = fold / tot;
    a = w0 * s;
    b = (w1 - w0) * s;
}

static __device__ __forceinline__ void fill_tables(int tid, float *tA512,
                                                   float *tB512, float *tA256,
                                                   float *tB256) {
    if (tid < 128) {
        int o = tid >> 4, t = tid & 15;
        float a, b;
        resize_ab(o, t, 64.f, 1.f / 64.f, 0.70710678118654752f, a, b);
        tA512[o * 17 + t] = a;
        tB512[o * 17 + t] = b;
    } else if (tid < 256) {
        int q = tid - 128;
        int o = q >> 4, t = q & 15;
        float a, b;
        resize_ab(o, t, 32.f, 1.f / 32.f, 0.5f, a, b);
        tA256[o * 17 + t] = a;
        tB256[o * 17 + t] = b;
    }
}

// ---------------------------------------------------------------------------
// Fused kernel: H-moment streaming + in-block W-axis resize. 512 threads.
// ---------------------------------------------------------------------------
__global__ void __launch_bounds__(512, 3) k1_fused(const float *__restrict__ x) {
    __shared__ float tA512[8 * 17], tB512[8 * 17], tA256[8 * 17], tB256[8 * 17];
    __shared__ float sm[16 * 64];  // [W-block t][mtH][wm]

    const int tid = threadIdx.x;
    const int img = blockIdx.y, b = blockIdx.x;
    fill_tables(tid, tA512, tB512, tA256, tB256);

    const float2 *xp = reinterpret_cast<const float2 *>(
                           x + (((size_t)img << 20) + ((size_t)b << 16))) +
                       tid;

    float2 s1 = {0, 0}, m1 = {0, 0}, s1h = {0, 0}, m1h = {0, 0};
    float2 s2 = {0, 0}, m2 = {0, 0}, s2h = {0, 0}, m2h = {0, 0};

#pragma unroll
    for (int pp = 0; pp < 16; pp++) {
        float2 r0 = xp[(pp * 4 + 0) << 9];
        float2 r1 = xp[(pp * 4 + 1) << 9];
        float2 r2 = xp[(pp * 4 + 2) << 9];
        float2 r3 = xp[(pp * 4 + 3) << 9];
        const float p0 = (float)(2 * pp), p1 = (float)(2 * pp + 1);
        const float fpp = (float)pp;

#define COMP(f)                                      \
    {                                                \
        float lo0 = r0.f + r1.f, hi0 = r0.f - r1.f;  \
        float lo1 = r2.f + r3.f, hi1 = r2.f - r3.f;  \
        s1.f += lo0 + lo1;                           \
        m1.f = fmaf(p0, lo0, m1.f);                  \
        m1.f = fmaf(p1, lo1, m1.f);                  \
        s1h.f += hi0 + hi1;                          \
        m1h.f = fmaf(p0, hi0, m1h.f);                \
        m1h.f = fmaf(p1, hi1, m1h.f);                \
        float lo2 = lo0 + lo1, hi2 = lo0 - lo1;      \
        s2.f += lo2;                                 \
        m2.f = fmaf(fpp, lo2, m2.f);                 \
        s2h.f += hi2;                                \
        m2h.f = fmaf(fpp, hi2, m2h.f);               \
    }
        COMP(x) COMP(y)
#undef COMP
    }

    // ---- W-axis epilogue ----
    // Thread owns cols (2*tid, 2*tid+1) = W-level1 pair j=tid; level2 index
    // i=tid>>1 via lane-parity pairing. Warp = W-block t (32 pairs / block).
    const int lane = tid & 31;
    const float u1loc = (float)lane;            // level1 in-block index
    const float u2loc = (float)((tid >> 1) & 15);  // level2 in-block index
    const bool even = !(tid & 1);
    float *smrow = sm + (tid >> 5) * 64;
    const int widx =
        ((lane >> 4) & 1) * 4 + ((lane >> 3) & 1) * 2 + ((lane >> 2) & 1);
    const bool storer = (lane & 3) == 0;

#define BFLY(d, half)                                              \
    _Pragma("unroll") for (int i = 0; i < half; i++) {             \
        bool up = (lane & d) != 0;                                 \
        float send = up ? v[i] : v[i + half];                      \
        float o_ = __shfl_xor_sync(FULLMASK, send, d);             \
        v[i] = (up ? v[i + half] : v[i]) + o_;                     \
    }

#define CHUNK(c, M)                                                \
    {                                                              \
        float l = M.x + M.y, h = M.x - M.y;                        \
        float v[8];                                                \
        v[0] = l;                                                  \
        v[1] = u1loc * l;                                          \
        v[2] = h;                                                  \
        v[3] = u1loc * h;                                          \
        float pl = __shfl_xor_sync(FULLMASK, l, 1);                \
        float lo2 = even ? (l + pl) : 0.f;                         \
        float hi2 = even ? (l - pl) : 0.f;                         \
        v[4] = lo2;                                                \
        v[5] = u2loc * lo2;                                        \
        v[6] = hi2;                                                \
        v[7] = u2loc * hi2;                                        \
        BFLY(16, 4) BFLY(8, 2) BFLY(4, 1)                          \
        v[0] += __shfl_xor_sync(FULLMASK, v[0], 2);                \
        v[0] += __shfl_xor_sync(FULLMASK, v[0], 1);                \
        if (storer) smrow[(c) * 8 + widx] = v[0];                  \
    }

    CHUNK(0, s1) CHUNK(1, m1) CHUNK(2, s1h) CHUNK(3, m1h)
    CHUNK(4, s2) CHUNK(5, m2) CHUNK(6, s2h) CHUNK(7, m2h)
#undef CHUNK
#undef BFLY

    __syncthreads();

    // Final combine: thread = (mtH = tid>>5, z = tid&31), z = g*8+o.
    // wm pairs: g0(lo2res,256)->4,5  g1(hi2res,256)->6,7
    //           g2(lo1res,512)->0,1  g3(hi1res,512)->2,3
    if (tid < 256) {
        int mtH = tid >> 5, z = tid & 31, g = z >> 3, o = z & 7;
        const float *A = (g < 2) ? tA256 : tA512;
        const float *B = (g < 2) ? tB256 : tB512;
        int wb = (g & 2) ? ((g & 1) ? 2 : 0) : ((g & 1) ? 6 : 4);
        const float *base = sm + mtH * 8 + wb;
        float acc = 0.f;
#pragma unroll
        for (int t = 0; t < 16; t++)
            acc = fmaf(A[o * 17 + t], base[t * 64],
                       fmaf(B[o * 17 + t], base[t * 64 + 1], acc));
        g_V[(((size_t)(img * 16 + b)) << 8) + tid] = acc;
    }
}

// ---------------------------------------------------------------------------
// Kernel 3: per (image, p-group): V -> Y[32][32] -> 7 maps -> GEMM.
// ---------------------------------------------------------------------------
__global__ void __launch_bounds__(256)
    k3_outpass(const float *__restrict__ Wg, const float *__restrict__ bias,
               float *__restrict__ out) {
    __shared__ float tA512[8 * 17], tB512[8 * 17], tA256[8 * 17], tB256[8 * 17];
    __shared__ float Vs[4096];     // [16 blocks][8 mt][32 z]
    __shared__ float Ys[32 * 33];

    int tid = threadIdx.x;
    int img = blockIdx.x;
    int pg = blockIdx.y;
    fill_tables(tid, tA512, tB512, tA256, tB256);
    {
        const float4 *vg =
            reinterpret_cast<const float4 *>(g_V + ((size_t)img << 12));
        float4 *vs = reinterpret_cast<float4 *>(Vs);
#pragma unroll
        for (int i = 0; i < 4; i++) vs[tid + (i << 8)] = vg[tid + (i << 8)];
    }
    __syncthreads();

    // Stage 2: Y[ri][cb..cb+3]. Row groups -> H moment types:
    // gr0->(s2,m2)@4 gr1->(s2h,m2h)@6 gr2->(s1,m1)@0 gr3->(s1h,m1h)@2
    int ri = tid >> 3;
    int gr = ri >> 3, o = ri & 7;
    int cb = (tid & 7) << 2;
    const float *A = (gr < 2) ? tA256 : tA512;
    const float *B = (gr < 2) ? tB256 : tB512;
    int smt = ((gr < 2) ? 4 : 0) + ((gr & 1) << 1);
    float a0 = 0, a1 = 0, a2 = 0, a3 = 0;
#pragma unroll
    for (int t = 0; t < 16; t++) {
        float av = A[o * 17 + t], bv = B[o * 17 + t];
        const float *S = Vs + ((t << 3) + smt) * 32 + cb;
        const float *M = S + 32;
        a0 = fmaf(av, S[0], fmaf(bv, M[0], a0));
        a1 = fmaf(av, S[1], fmaf(bv, M[1], a1));
        a2 = fmaf(av, S[2], fmaf(bv, M[2], a2));
        a3 = fmaf(av, S[3], fmaf(bv, M[3], a3));
    }
    Ys[ri * 33 + cb + 0] = a0;
    Ys[ri * 33 + cb + 1] = a1;
    Ys[ri * 33 + cb + 2] = a2;
    Ys[ri * 33 + cb + 3] = a3;
    __syncthreads();

    // Stage 3: (rowgroup,colgroup) map:
    // cA2(0,0) cH2(1,0) cV2(0,1) cD2(1,1) cH1(3,2) cV1(2,3) cD1(3,3)
    float w0 = Wg[tid], w1 = Wg[256 + tid], w2 = Wg[512 + tid],
          w3 = Wg[768 + tid], w4 = Wg[1024 + tid], w5 = Wg[1280 + tid],
          w6 = Wg[1536 + tid];
    float bb = bias[tid];
    float *op = out + ((size_t)img << 14) + tid;
    int p0 = pg << 4;
#pragma unroll
    for (int q = 0; q < 16; q++) {
        int p = p0 + q;
        int i = p >> 3, j = p & 7;
        float v = bb;
        v = fmaf(Ys[(0 + i) * 33 + (0 + j)], w0, v);
        v = fmaf(Ys[(8 + i) * 33 + (0 + j)], w1, v);
        v = fmaf(Ys[(0 + i) * 33 + (8 + j)], w2, v);
        v = fmaf(Ys[(8 + i) * 33 + (8 + j)], w3, v);
        v = fmaf(Ys[(24 + i) * 33 + (16 + j)], w4, v);
        v = fmaf(Ys[(16 + i) * 33 + (24 + j)], w5, v);
        v = fmaf(Ys[(24 + i) * 33 + (24 + j)], w6, v);
        op[(size_t)p << 8] = v;
    }
}

extern "C" void kernel_launch(void *const *d_in, const int *in_sizes, int n_in,
                              void *d_out, int out_size) {
    const float *x = (const float *)d_in[0];     // [64,1,1024,1024]
    const float *W = (const float *)d_in[1];     // [7,256]
    const float *bias = (const float *)d_in[2];  // [256]
    float *out = (float *)d_out;                 // [64,64,256]

    dim3 g1(16, 64);
    k1_fused<<<g1, 512>>>(x);
    dim3 g3(64, 4);
    k3_outpass<<<g3, 256>>>(W, bias, out);
}

// round 6
// speedup vs baseline: 1.0673x; 1.0673x over previous
#include <cuda_runtime.h>

// ---------------------------------------------------------------------------
// WaveletEncoder: 2-level Haar wavedec2 -> bilinear(antialias) resize to 8x8
// -> stack 7 maps -> [B,64,7] @ W[7,256] + b.
//
// All-linear separable pipeline; axes commute; triangle antialias resize
// weight is linear within blocks of K/2 samples => per-block (sum, moment).
//
// Round-6: ONE kernel. Per (img, 64-row block):
//   - stream 64 rows, accumulate 7 H-axis moment types per column (s2==s1
//     identity removes the 8th), float4 per thread
//   - W-axis Haar intra-thread -> 16 W-partials per H-moment chunk -> 16-lane
//     butterfly reduce -> smem -> 256-thread coefficient combine -> V[imgb]
//   - last-block-per-image (atomic counter, monotonic so replay-safe) runs
//     the output stage: V -> Y[32][32] -> 7 maps' 8x8 -> GEMM W[7,256]+b.
// ---------------------------------------------------------------------------

#define FULLMASK 0xffffffffu

__device__ float g_V[64u * 16u * 8u * 32u];  // 1 MB [imgb][8 mtH][32 z]
__device__ unsigned g_ctr[64];               // per-image arrival counters

static __device__ __forceinline__ void resize_ab(int o, int t, float K,
                                                 float invK, float fold,
                                                 float &a, float &b) {
    float tot = K * ((o == 0 || o == 7) ? 0.875f : 1.0f);
    float sf = (o + 0.5f) * K - 0.5f;
    float i0 = t * (K * 0.5f);
    float w0 = fmaxf(0.f, 1.f - fabsf(sf - i0) * invK);
    float w1 = fmaxf(0.f, 1.f - fabsf(sf - (i0 + 1.f)) * invK);
    float s = fold / tot;
    a = w0 * s;
    b = (w1 - w0) * s;
}

static __device__ __forceinline__ void fill_tables(int tid, float *tA512,
                                                   float *tB512, float *tA256,
                                                   float *tB256) {
    if (tid < 128) {
        int o = tid >> 4, t = tid & 15;
        float a, b;
        resize_ab(o, t, 64.f, 1.f / 64.f, 0.70710678118654752f, a, b);
        tA512[o * 17 + t] = a;
        tB512[o * 17 + t] = b;
    } else if (tid < 256) {
        int q = tid - 128;
        int o = q >> 4, t = q & 15;
        float a, b;
        resize_ab(o, t, 32.f, 1.f / 32.f, 0.5f, a, b);
        tA256[o * 17 + t] = a;
        tB256[o * 17 + t] = b;
    }
}

__global__ void __launch_bounds__(256, 4)
    k1_fused(const float *__restrict__ x, const float *__restrict__ Wg,
             const float *__restrict__ bias, float *__restrict__ out) {
    __shared__ float tA512[8 * 17], tB512[8 * 17], tA256[8 * 17], tB256[8 * 17];
    __shared__ float sm[16 * 64];  // [W-block t][chunk c][16 partials]
    __shared__ float Vs[4096];     // k3: [16 blocks][8 mt][32 z]
    __shared__ float Ys[32 * 33];  // k3: combined Y
    __shared__ int sIsLast;

    const int tid = threadIdx.x;
    const int img = blockIdx.y, b = blockIdx.x;
    fill_tables(tid, tA512, tB512, tA256, tB256);

    const float4 *xp = reinterpret_cast<const float4 *>(
                           x + (((size_t)img << 20) + ((size_t)b << 16))) +
                       tid;

    float4 s1 = {0, 0, 0, 0}, m1 = {0, 0, 0, 0};
    float4 s1h = {0, 0, 0, 0}, m1h = {0, 0, 0, 0};
    float4 m2 = {0, 0, 0, 0};
    float4 s2h = {0, 0, 0, 0}, m2h = {0, 0, 0, 0};

#pragma unroll
    for (int pp = 0; pp < 16; pp++) {
        float4 r0 = xp[(pp * 4 + 0) << 8];
        float4 r1 = xp[(pp * 4 + 1) << 8];
        float4 r2 = xp[(pp * 4 + 2) << 8];
        float4 r3 = xp[(pp * 4 + 3) << 8];
        const float p0 = (float)(2 * pp), p1 = (float)(2 * pp + 1);
        const float fpp = (float)pp;

#define COMP(f)                                       \
    {                                                 \
        float lo0 = r0.f + r1.f, hi0 = r0.f - r1.f;   \
        float lo1 = r2.f + r3.f, hi1 = r2.f - r3.f;   \
        s1.f += lo0 + lo1;                            \
        m1.f = fmaf(p0, lo0, m1.f);                   \
        m1.f = fmaf(p1, lo1, m1.f);                   \
        s1h.f += hi0 + hi1;                           \
        m1h.f = fmaf(p0, hi0, m1h.f);                 \
        m1h.f = fmaf(p1, hi1, m1h.f);                 \
        float lo2 = lo0 + lo1, hi2 = lo0 - lo1;       \
        m2.f = fmaf(fpp, lo2, m2.f);                  \
        s2h.f += hi2;                                 \
        m2h.f = fmaf(fpp, hi2, m2h.f);                \
    }
        COMP(x) COMP(y) COMP(z) COMP(w)
#undef COMP
    }

    // ---- W-axis epilogue (R4 structure; s2 == s1 identity) ----
    const float u0 = (float)((2 * tid) & 31), u1 = u0 + 1.f;
    const float u2 = (float)(tid & 15);
    const int lane4 = tid & 15;
    float *smrow = sm + (tid >> 4) * 64;

#define CHUNK(c, A4, B4)                                                    \
    {                                                                       \
        float v[16];                                                        \
        {                                                                   \
            float l0 = A4.x + A4.y, h0 = A4.x - A4.y;                       \
            float l1 = A4.z + A4.w, h1 = A4.z - A4.w;                       \
            v[0] = l0 + l1;                                                 \
            v[1] = fmaf(u0, l0, u1 * l1);                                   \
            v[2] = h0 + h1;                                                 \
            v[3] = fmaf(u0, h0, u1 * h1);                                   \
            float lo2 = l0 + l1, hi2 = l0 - l1;                             \
            v[4] = lo2;                                                     \
            v[5] = u2 * lo2;                                                \
            v[6] = hi2;                                                     \
            v[7] = u2 * hi2;                                                \
        }                                                                   \
        {                                                                   \
            float l0 = B4.x + B4.y, h0 = B4.x - B4.y;                       \
            float l1 = B4.z + B4.w, h1 = B4.z - B4.w;                       \
            v[8] = l0 + l1;                                                 \
            v[9] = fmaf(u0, l0, u1 * l1);                                   \
            v[10] = h0 + h1;                                                \
            v[11] = fmaf(u0, h0, u1 * h1);                                  \
            float lo2 = l0 + l1, hi2 = l0 - l1;                             \
            v[12] = lo2;                                                    \
            v[13] = u2 * lo2;                                               \
            v[14] = hi2;                                                    \
            v[15] = u2 * hi2;                                               \
        }                                                                   \
        _Pragma("unroll") for (int d = 8; d >= 1; d >>= 1) {                \
            bool up = (tid & d) != 0;                                       \
            _Pragma("unroll") for (int i = 0; i < d; i++) {                 \
                float send = up ? v[i] : v[i + d];                          \
                float other = __shfl_xor_sync(FULLMASK, send, d);           \
                v[i] = (up ? v[i + d] : v[i]) + other;                      \
            }                                                               \
        }                                                                   \
        smrow[(c) * 16 + lane4] = v[0];                                     \
    }

    CHUNK(0, s1, m1)
    CHUNK(1, s1h, m1h)
    CHUNK(2, s1, m2)   // s2 == s1
    CHUNK(3, s2h, m2h)
#undef CHUNK

    __syncthreads();

    // Final combine -> g_V. Thread = (mtH = tid>>5, z = tid&31), z = g*8+o.
    {
        int mtH = tid >> 5, z = tid & 31, g = z >> 3, o = z & 7;
        const float *A = (g < 2) ? tA256 : tA512;
        const float *B = (g < 2) ? tB256 : tB512;
        int wb = (g & 2) ? ((g & 1) ? 2 : 0) : ((g & 1) ? 6 : 4);
        const float *base = sm + mtH * 16 + (mtH & 1) * 0 + wb;
        // layout identical to R4: sm[t][(mtH>>1)*16 + (mtH&1)*8 + w]
        base = sm + (mtH >> 1) * 16 + (mtH & 1) * 8 + wb;
        float acc = 0.f;
#pragma unroll
        for (int t = 0; t < 16; t++)
            acc = fmaf(A[o * 17 + t], base[t * 64],
                       fmaf(B[o * 17 + t], base[t * 64 + 1], acc));
        g_V[(((size_t)(img * 16 + b)) << 8) + tid] = acc;
    }

    // ---- last-block-per-image detection ----
    __threadfence();
    __syncthreads();
    if (tid == 0) {
        unsigned old = atomicAdd(&g_ctr[img], 1u);
        sIsLast = ((old & 15u) == 15u) ? 1 : 0;
    }
    __syncthreads();
    if (!sIsLast) return;
    __threadfence();

    // ---- output stage (k3 body) for this image ----
    {
        const float4 *vg =
            reinterpret_cast<const float4 *>(g_V + ((size_t)img << 12));
        float4 *vs = reinterpret_cast<float4 *>(Vs);
#pragma unroll
        for (int i = 0; i < 4; i++) vs[tid + (i << 8)] = vg[tid + (i << 8)];
    }
    __syncthreads();

    // Stage 2: Y[ri][cb..cb+3]. Row groups -> H moment types:
    // gr0->(s2,m2)@4 gr1->(s2h,m2h)@6 gr2->(s1,m1)@0 gr3->(s1h,m1h)@2
    {
        int ri = tid >> 3;
        int gr = ri >> 3, o = ri & 7;
        int cb = (tid & 7) << 2;
        const float *A = (gr < 2) ? tA256 : tA512;
        const float *B = (gr < 2) ? tB256 : tB512;
        int smt = ((gr < 2) ? 4 : 0) + ((gr & 1) << 1);
        float a0 = 0, a1 = 0, a2 = 0, a3 = 0;
#pragma unroll
        for (int t = 0; t < 16; t++) {
            float av = A[o * 17 + t], bv = B[o * 17 + t];
            const float *S = Vs + ((t << 3) + smt) * 32 + cb;
            const float *M = S + 32;
            a0 = fmaf(av, S[0], fmaf(bv, M[0], a0));
            a1 = fmaf(av, S[1], fmaf(bv, M[1], a1));
            a2 = fmaf(av, S[2], fmaf(bv, M[2], a2));
            a3 = fmaf(av, S[3], fmaf(bv, M[3], a3));
        }
        Ys[ri * 33 + cb + 0] = a0;
        Ys[ri * 33 + cb + 1] = a1;
        Ys[ri * 33 + cb + 2] = a2;
        Ys[ri * 33 + cb + 3] = a3;
    }
    __syncthreads();

    // Stage 3: (rowgroup,colgroup) map:
    // cA2(0,0) cH2(1,0) cV2(0,1) cD2(1,1) cH1(3,2) cV1(2,3) cD1(3,3)
    {
        float w0 = Wg[tid], w1 = Wg[256 + tid], w2 = Wg[512 + tid],
              w3 = Wg[768 + tid], w4 = Wg[1024 + tid], w5 = Wg[1280 + tid],
              w6 = Wg[1536 + tid];
        float bb = bias[tid];
        float *op = out + ((size_t)img << 14) + tid;
#pragma unroll
        for (int p = 0; p < 64; p++) {
            int i = p >> 3, j = p & 7;
            float v = bb;
            v = fmaf(Ys[(0 + i) * 33 + (0 + j)], w0, v);
            v = fmaf(Ys[(8 + i) * 33 + (0 + j)], w1, v);
            v = fmaf(Ys[(0 + i) * 33 + (8 + j)], w2, v);
            v = fmaf(Ys[(8 + i) * 33 + (8 + j)], w3, v);
            v = fmaf(Ys[(24 + i) * 33 + (16 + j)], w4, v);
            v = fmaf(Ys[(16 + i) * 33 + (24 + j)], w5, v);
            v = fmaf(Ys[(24 + i) * 33 + (24 + j)], w6, v);
            op[(size_t)p << 8] = v;
        }
    }
}

extern "C" void kernel_launch(void *const *d_in, const int *in_sizes, int n_in,
                              void *d_out, int out_size) {
    const float *x = (const float *)d_in[0];     // [64,1,1024,1024]
    const float *W = (const float *)d_in[1];     // [7,256]
    const float *bias = (const float *)d_in[2];  // [256]
    float *out = (float *)d_out;                 // [64,64,256]

    dim3 g1(16, 64);
    k1_fused<<<g1, 256>>>(x, W, bias, out);
}